// round 5
// baseline (speedup 1.0000x reference)
#include <cuda_runtime.h>
#include <cstdint>

#define FULL 0xffffffffu

constexpr int   NTAG    = 32;
constexpr int   CH      = 8;              // steps per chunk
constexpr int   NS      = 4;              // ring slots (chunks)
constexpr int   D       = 2;              // chunks prefetched ahead
constexpr int   STEPF   = NTAG * NTAG;    // 1024 floats per step
constexpr int   CHUNK_B = CH * STEPF * 4; // 32768 bytes
constexpr float NEGINF  = -1e4f;

__device__ __forceinline__ void cp16(uint32_t dst, const void* src) {
    asm volatile("cp.async.cg.shared.global [%0], [%1], 16;" :: "r"(dst), "l"(src) : "memory");
}
__device__ __forceinline__ void cp_commit() {
    asm volatile("cp.async.commit_group;" ::: "memory");
}
template<int N> __device__ __forceinline__ void cp_wait() {
    asm volatile("cp.async.wait_group %0;" :: "n"(N) : "memory");
}
__device__ __forceinline__ void barsync() {
    asm volatile("bar.sync 0;" ::: "memory");
}

// bool-array accessor: mode 0 = int32, 1 = uint8, 2 = float32
__device__ __forceinline__ bool getb(const void* p, int idx, int mode) {
    if (mode == 0) return ((const int*)p)[idx] != 0;
    if (mode == 1) return ((const uint8_t*)p)[idx] != 0;
    return ((const float*)p)[idx] != 0.0f;
}

// One Viterbi step for lane j: over i of s[i] = alpha[i] + ((phi[i][j]+tp[i]) [+ep]).
// - best: max via pure FMNMX tree (lat-4 chain) -> feeds the serial recurrence.
// - bidx: first-argmax via left-biased select tree -> feeds only the backpointer
//   store, off the critical path. Float op order replicates the reference
//   exactly so argmax ties match bitwise; FMNMX max == select-tree max bitwise.
template<bool END>
__device__ __forceinline__ void vstep(const float* __restrict__ ph, const float* tp,
                                      float my_alpha, float epj, float& best, int& bidx)
{
    float s[NTAG];
#pragma unroll
    for (int i = 0; i < NTAG; ++i) {
        float av = __shfl_sync(FULL, my_alpha, i);
        float e  = ph[i * NTAG] + tp[i];
        if (END) e += epj;
        s[i] = av + e;
    }

    // ---- value: FMNMX tree (critical path) ----
    float m[16];
#pragma unroll
    for (int k = 0; k < 16; ++k) m[k] = fmaxf(s[2*k], s[2*k+1]);
#pragma unroll
    for (int k = 0; k < 8; ++k)  m[k] = fmaxf(m[2*k], m[2*k+1]);
#pragma unroll
    for (int k = 0; k < 4; ++k)  m[k] = fmaxf(m[2*k], m[2*k+1]);
#pragma unroll
    for (int k = 0; k < 2; ++k)  m[k] = fmaxf(m[2*k], m[2*k+1]);
    best = fmaxf(m[0], m[1]);

    // ---- index: left-biased select tree (off critical path) ----
    float v[16]; int ix[16];
#pragma unroll
    for (int k = 0; k < 16; ++k) {
        bool c = s[2*k+1] > s[2*k];
        v[k] = c ? s[2*k+1] : s[2*k];  ix[k] = c ? 2*k+1 : 2*k;
    }
#pragma unroll
    for (int k = 0; k < 8; ++k) {
        bool c = v[2*k+1] > v[2*k];
        v[k] = c ? v[2*k+1] : v[2*k];  ix[k] = c ? ix[2*k+1] : ix[2*k];
    }
#pragma unroll
    for (int k = 0; k < 4; ++k) {
        bool c = v[2*k+1] > v[2*k];
        v[k] = c ? v[2*k+1] : v[2*k];  ix[k] = c ? ix[2*k+1] : ix[2*k];
    }
#pragma unroll
    for (int k = 0; k < 2; ++k) {
        bool c = v[2*k+1] > v[2*k];
        v[k] = c ? v[2*k+1] : v[2*k];  ix[k] = c ? ix[2*k+1] : ix[2*k];
    }
    bidx = (v[1] > v[0]) ? ix[1] : ix[0];
}

__global__ void __launch_bounds__(64, 1)
ConstrainedDecoder_kernel(const float* __restrict__ lp,
                          const void* __restrict__ mask,
                          const void* __restrict__ startc,
                          const void* __restrict__ endc,
                          const void* __restrict__ transc,
                          float* __restrict__ out,
                          int B, int T)
{
    extern __shared__ char smem[];
    float*   buf  = (float*)smem;                         // NS * 32KB = 128KB ring
    uint8_t* back = (uint8_t*)(smem + NS * CHUNK_B);      // T * 32 bytes

    const int b   = blockIdx.x;
    const int tid = threadIdx.x;
    const int j   = tid & 31;
    const int wid = tid >> 5;

    // ---- detect bool encoding from mask[0] (guaranteed true) ----
    uint32_t w0 = ((const uint32_t*)mask)[0];
    const int mode = (w0 == 1u) ? 0 : (w0 == 0x01010101u) ? 1 : 2;

    // ---- sequence length (mask prefix-true); computed by both warps ----
    int len = 0;
    {
        const size_t mbase = (size_t)b * T;
        for (int k = j; k < T; k += 32)
            if (getb(mask, (int)(mbase + k), mode)) len = k + 1;
#pragma unroll
        for (int off = 16; off; off >>= 1)
            len = max(len, __shfl_xor_sync(FULL, len, off));
    }
    if (len < 1) len = 1;
    if (len > T) len = T;
    const int nchunk = (len + CH - 1) / CH;
    const int lenm1  = len - 1;

    if (wid == 1) {
        // =================== producer warp ===================
        const char*    g     = (const char*)(lp + (size_t)b * T * STEPF);
        const uint32_t sbase = (uint32_t)__cvta_generic_to_shared(buf);
        const size_t   limit = (size_t)T * STEPF * 4;   // bytes in this batch row

        // issue chunk cc into slot cc % NS, one commit group per chunk
        auto issue = [&](int cc) {
            size_t   goff = (size_t)cc * CHUNK_B;
            uint32_t dst  = sbase + (uint32_t)(cc & (NS - 1)) * CHUNK_B + (uint32_t)j * 16;
            const char* gs = g + goff + (size_t)j * 16;
#pragma unroll 4
            for (int r = 0; r < CHUNK_B / 512; ++r) {
                if (goff + (size_t)r * 512 + (size_t)j * 16 < limit)
                    cp16(dst + r * 512, gs + r * 512);
            }
            cp_commit();
        };

        int pre = nchunk < D ? nchunk : D;
        for (int cc = 0; cc < pre; ++cc) issue(cc);
        for (int cc = pre; cc < D; ++cc) cp_commit();   // pad to exactly D groups

        for (int c = 0; c < nchunk; ++c) {
            if (c + D < nchunk) issue(c + D); else cp_commit();
            cp_wait<D>();          // oldest group (chunk c) now complete
            barsync();             // release compute into chunk c
        }
    } else {
        // =================== compute warp ===================
        const float sp = getb(startc, j, mode) ? 0.0f : NEGINF;
        const float ep = getb(endc,   j, mode) ? 0.0f : NEGINF;
        float tp[NTAG];
#pragma unroll
        for (int i = 0; i < NTAG; ++i)
            tp[i] = getb(transc, i * NTAG + j, mode) ? 0.0f : NEGINF;

        float    my_alpha = 0.0f;
        uint8_t* bk = back + j;

        for (int c = 0; c < nchunk; ++c) {
            barsync();   // chunk c is resident
            const float* pb = buf + (size_t)(c & (NS - 1)) * CH * STEPF + j;

            int t0 = c * CH;
            int t1 = t0 + CH; if (t1 > len) t1 = len;

            if (c == 0) {
                // t = 0: alpha0[j] = max_i phi0[i][j] + sp[j] (+ ep[j] if len == 1)
                float m = pb[0];
#pragma unroll
                for (int i = 1; i < NTAG; ++i) m = fmaxf(m, pb[i * NTAG]);
                my_alpha = m + sp;
                if (len == 1) my_alpha += ep;
                t0 = 1;
            }

            int tend = t1 < lenm1 ? t1 : lenm1;   // hot steps exclude the end step
#pragma unroll 2
            for (int t = t0; t < tend; ++t) {
                const float* ph = pb + (size_t)(t & (CH - 1)) * STEPF;
                float best; int bi;
                vstep<false>(ph, tp, my_alpha, ep, best, bi);
                my_alpha = best;
                bk[(size_t)t * NTAG] = (uint8_t)bi;
            }

            if (len >= 2 && (lenm1 >> 3) == c) {
                const float* ph = pb + (size_t)(lenm1 & (CH - 1)) * STEPF;
                float best; int bi;
                vstep<true>(ph, tp, my_alpha, ep, best, bi);
                my_alpha = best;
                bk[(size_t)lenm1 * NTAG] = (uint8_t)bi;
            }
        }

        // ---- final max / first-argmax over tags ----
        __syncwarp();
        float v = my_alpha; int ix = j;
#pragma unroll
        for (int off = 16; off; off >>= 1) {
            float ov = __shfl_xor_sync(FULL, v, off);
            int   oi = __shfl_xor_sync(FULL, ix, off);
            if (ov > v || (ov == v && oi < ix)) { v = ov; ix = oi; }
        }

        float* out_mlp  = out;       // [B]
        float* out_tags = out + B;   // [B, T]
        if (j == 0) out_mlp[b] = v;

        for (int k = len + j; k < T; k += 32)
            out_tags[(size_t)b * T + k] = -1.0f;

        // ---- backtrack (lane 0, sequential smem chain) ----
        if (j == 0) {
            int tag = ix;
            out_tags[(size_t)b * T + lenm1] = (float)tag;
            for (int tt = lenm1; tt >= 1; --tt) {
                tag = back[(size_t)tt * NTAG + tag];
                out_tags[(size_t)b * T + tt - 1] = (float)tag;
            }
        }
    }
}

extern "C" void kernel_launch(void* const* d_in, const int* in_sizes, int n_in,
                              void* d_out, int out_size)
{
    const float* lp   = (const float*)d_in[0];
    const void*  mask = d_in[1];
    const void*  sc   = d_in[2];
    const void*  ec   = d_in[3];
    const void*  tc   = d_in[4];

    const int BT = in_sizes[1];      // B*T elements in mask
    int B = out_size - BT;           // out = [B] mlp + [B*T] tags
    if (B <= 0) B = 64;
    const int T = BT / B;

    size_t smem = (size_t)NS * CHUNK_B + (size_t)T * NTAG;
    cudaFuncSetAttribute(ConstrainedDecoder_kernel,
                         cudaFuncAttributeMaxDynamicSharedMemorySize, (int)smem);

    ConstrainedDecoder_kernel<<<B, 64, smem>>>(lp, mask, sc, ec, tc,
                                               (float*)d_out, B, T);
}

// round 7
// speedup vs baseline: 1.0068x; 1.0068x over previous
#include <cuda_runtime.h>
#include <cstdint>

#define FULL 0xffffffffu

constexpr int   NTAG    = 32;
constexpr int   CH      = 8;              // steps per chunk
constexpr int   NS      = 4;              // phi ring slots (chunks)
constexpr int   STEPF   = NTAG * NTAG;    // 1024 floats per step
constexpr int   CHUNK_B = CH * STEPF * 4; // 32768 bytes
constexpr int   ARING   = 24;             // alpha ring slots (steps)
constexpr float NEGINF  = -1e4f;

__device__ __forceinline__ void cp16(uint32_t dst, const void* src) {
    asm volatile("cp.async.cg.shared.global [%0], [%1], 16;" :: "r"(dst), "l"(src) : "memory");
}
__device__ __forceinline__ void cp_commit() {
    asm volatile("cp.async.commit_group;" ::: "memory");
}
template<int N> __device__ __forceinline__ void cp_wait() {
    asm volatile("cp.async.wait_group %0;" :: "n"(N) : "memory");
}
__device__ __forceinline__ void barsync() {
    asm volatile("bar.sync 0;" ::: "memory");
}

// bool-array accessor: mode 0 = int32, 1 = uint8, 2 = float32
__device__ __forceinline__ bool getb(const void* p, int idx, int mode) {
    if (mode == 0) return ((const int*)p)[idx] != 0;
    if (mode == 1) return ((const uint8_t*)p)[idx] != 0;
    return ((const float*)p)[idx] != 0.0f;
}

// ---- value-only step (compute warp): max_i alpha[i] + ((phi[i][j]+tp[i]) [+ep]) ----
// FMNMX tree; bitwise equal to reference max (no NaNs). Op order matches reference.
template<bool END>
__device__ __forceinline__ float vval(const float* __restrict__ ph, const float* tp,
                                      float my_alpha, float epj)
{
    float s[NTAG];
#pragma unroll
    for (int i = 0; i < NTAG; ++i) {
        float av = __shfl_sync(FULL, my_alpha, i);
        float e  = ph[i * NTAG] + tp[i];
        if (END) e += epj;
        s[i] = av + e;
    }
    float m[16];
#pragma unroll
    for (int k = 0; k < 16; ++k) m[k] = fmaxf(s[2*k], s[2*k+1]);
#pragma unroll
    for (int k = 0; k < 8; ++k)  m[k] = fmaxf(m[2*k], m[2*k+1]);
#pragma unroll
    for (int k = 0; k < 4; ++k)  m[k] = fmaxf(m[2*k], m[2*k+1]);
#pragma unroll
    for (int k = 0; k < 2; ++k)  m[k] = fmaxf(m[2*k], m[2*k+1]);
    return fmaxf(m[0], m[1]);
}

// ---- index-only step (argmax warp): first-argmax via left-biased select tree ----
// Recomputes s[i] with identical float op order -> identical comparisons.
template<bool END>
__device__ __forceinline__ int vidx(const float* __restrict__ ph, const float* tp,
                                    float a_self, float epj)
{
    float s[NTAG];
#pragma unroll
    for (int i = 0; i < NTAG; ++i) {
        float av = __shfl_sync(FULL, a_self, i);
        float e  = ph[i * NTAG] + tp[i];
        if (END) e += epj;
        s[i] = av + e;
    }
    float v[16]; int ix[16];
#pragma unroll
    for (int k = 0; k < 16; ++k) {
        bool c = s[2*k+1] > s[2*k];
        v[k] = c ? s[2*k+1] : s[2*k];  ix[k] = c ? 2*k+1 : 2*k;
    }
#pragma unroll
    for (int k = 0; k < 8; ++k) {
        bool c = v[2*k+1] > v[2*k];
        v[k] = c ? v[2*k+1] : v[2*k];  ix[k] = c ? ix[2*k+1] : ix[2*k];
    }
#pragma unroll
    for (int k = 0; k < 4; ++k) {
        bool c = v[2*k+1] > v[2*k];
        v[k] = c ? v[2*k+1] : v[2*k];  ix[k] = c ? ix[2*k+1] : ix[2*k];
    }
#pragma unroll
    for (int k = 0; k < 2; ++k) {
        bool c = v[2*k+1] > v[2*k];
        v[k] = c ? v[2*k+1] : v[2*k];  ix[k] = c ? ix[2*k+1] : ix[2*k];
    }
    return (v[1] > v[0]) ? ix[1] : ix[0];
}

__global__ void __launch_bounds__(96, 1)
ConstrainedDecoder_kernel(const float* __restrict__ lp,
                          const void* __restrict__ mask,
                          const void* __restrict__ startc,
                          const void* __restrict__ endc,
                          const void* __restrict__ transc,
                          float* __restrict__ out,
                          int B, int T)
{
    extern __shared__ char smem[];
    float*   buf   = (float*)smem;                                   // NS*32KB phi ring
    float*   aring = (float*)(smem + NS * CHUNK_B);                  // ARING*32 floats
    uint8_t* back  = (uint8_t*)(smem + NS * CHUNK_B + ARING * NTAG * 4); // T*32 bytes
    int*     xsh   = (int*)(back + (size_t)T * NTAG);                // final tag index

    const int b   = blockIdx.x;
    const int tid = threadIdx.x;
    const int j   = tid & 31;
    const int wid = tid >> 5;   // 0=compute, 1=producer, 2=argmax

    // ---- detect bool encoding from mask[0] (guaranteed true) ----
    uint32_t w0 = ((const uint32_t*)mask)[0];
    const int mode = (w0 == 1u) ? 0 : (w0 == 0x01010101u) ? 1 : 2;

    // ---- sequence length (mask prefix-true); all warps compute it ----
    int len = 0;
    {
        const size_t mbase = (size_t)b * T;
        for (int k = j; k < T; k += 32)
            if (getb(mask, (int)(mbase + k), mode)) len = k + 1;
#pragma unroll
        for (int off = 16; off; off >>= 1)
            len = max(len, __shfl_xor_sync(FULL, len, off));
    }
    if (len < 1) len = 1;
    if (len > T) len = T;
    const int nchunk = (len + CH - 1) / CH;
    const int lenm1  = len - 1;

    if (wid == 1) {
        // =================== producer warp ===================
        const char*    g     = (const char*)(lp + (size_t)b * T * STEPF);
        const uint32_t sbase = (uint32_t)__cvta_generic_to_shared(buf);
        const size_t   limit = (size_t)T * STEPF * 4;

        auto issue = [&](int cc) {
            size_t   goff = (size_t)cc * CHUNK_B;
            uint32_t dst  = sbase + (uint32_t)(cc & (NS - 1)) * CHUNK_B + (uint32_t)j * 16;
            const char* gs = g + goff + (size_t)j * 16;
#pragma unroll 4
            for (int r = 0; r < CHUNK_B / 512; ++r) {
                if (goff + (size_t)r * 512 + (size_t)j * 16 < limit)
                    cp16(dst + r * 512, gs + r * 512);
            }
            cp_commit();
        };

        issue(0);   // prologue: depth-1 prefetch (chunk 0)
        for (int c = 0; c <= nchunk; ++c) {
            if (c < nchunk) {
                if (c + 1 < nchunk) issue(c + 1); else cp_commit();
                cp_wait<1>();       // chunk c complete
            }
            barsync();
        }
        barsync();  // final output handoff bar
    } else if (wid == 0) {
        // =================== compute warp (value recurrence) ===================
        const float sp = getb(startc, j, mode) ? 0.0f : NEGINF;
        const float ep = getb(endc,   j, mode) ? 0.0f : NEGINF;
        float tp[NTAG];
#pragma unroll
        for (int i = 0; i < NTAG; ++i)
            tp[i] = getb(transc, i * NTAG + j, mode) ? 0.0f : NEGINF;

        float my_alpha = 0.0f;

        for (int c = 0; c <= nchunk; ++c) {
            barsync();   // chunk c resident
            if (c >= nchunk) continue;
            const float* pb = buf + (size_t)(c & (NS - 1)) * CH * STEPF + j;

            int t0 = c * CH;
            int t1 = t0 + CH; if (t1 > len) t1 = len;

            if (c == 0) {
                float m = pb[0];
#pragma unroll
                for (int i = 1; i < NTAG; ++i) m = fmaxf(m, pb[i * NTAG]);
                my_alpha = m + sp;
                if (len == 1) my_alpha += ep;
                aring[j] = my_alpha;   // slot 0
                t0 = 1;
            }

            int tend = t1 < lenm1 ? t1 : lenm1;
#pragma unroll 2
            for (int t = t0; t < tend; ++t) {
                const float* ph = pb + (size_t)(t & (CH - 1)) * STEPF;
                my_alpha = vval<false>(ph, tp, my_alpha, ep);
                aring[(t % ARING) * NTAG + j] = my_alpha;
            }

            if (len >= 2 && (lenm1 >> 3) == c) {
                const float* ph = pb + (size_t)(lenm1 & (CH - 1)) * STEPF;
                my_alpha = vval<true>(ph, tp, my_alpha, ep);
                aring[(lenm1 % ARING) * NTAG + j] = my_alpha;
            }
        }

        // final max / first-argmax over tags
        float v = my_alpha; int ix = j;
#pragma unroll
        for (int off = 16; off; off >>= 1) {
            float ov = __shfl_xor_sync(FULL, v, off);
            int   oi = __shfl_xor_sync(FULL, ix, off);
            if (ov > v || (ov == v && oi < ix)) { v = ov; ix = oi; }
        }
        if (j == 0) { out[b] = v; *xsh = ix; }
        barsync();  // final output handoff bar
    } else {
        // =================== argmax warp (backpointers, 1 chunk behind) ===================
        const float ep = getb(endc, j, mode) ? 0.0f : NEGINF;
        float tp[NTAG];
#pragma unroll
        for (int i = 0; i < NTAG; ++i)
            tp[i] = getb(transc, i * NTAG + j, mode) ? 0.0f : NEGINF;

        for (int c = 0; c <= nchunk; ++c) {
            barsync();
            int cc = c - 1;
            if (cc < 0) continue;
            const float* pb = buf + (size_t)(cc & (NS - 1)) * CH * STEPF + j;

            int t0 = cc * CH; if (t0 < 1) t0 = 1;
            int t1 = cc * CH + CH; if (t1 > len) t1 = len;
            int tend = t1 < lenm1 ? t1 : lenm1;

#pragma unroll 2
            for (int t = t0; t < tend; ++t) {
                const float* ph = pb + (size_t)(t & (CH - 1)) * STEPF;
                float a_self = aring[((t - 1) % ARING) * NTAG + j];
                int bi = vidx<false>(ph, tp, a_self, ep);
                back[(size_t)t * NTAG + j] = (uint8_t)bi;
            }

            if (len >= 2 && (lenm1 >> 3) == cc) {
                const float* ph = pb + (size_t)(lenm1 & (CH - 1)) * STEPF;
                float a_self = aring[((lenm1 - 1) % ARING) * NTAG + j];
                int bi = vidx<true>(ph, tp, a_self, ep);
                back[(size_t)lenm1 * NTAG + j] = (uint8_t)bi;
            }
        }

        barsync();  // xsh + back complete

        float* out_tags = out + B;   // [B, T]
        int ix = *xsh;

        for (int k = len + j; k < T; k += 32)
            out_tags[(size_t)b * T + k] = -1.0f;

        if (j == 0) {
            int tag = ix;
            out_tags[(size_t)b * T + lenm1] = (float)tag;
            for (int tt = lenm1; tt >= 1; --tt) {
                tag = back[(size_t)tt * NTAG + tag];
                out_tags[(size_t)b * T + tt - 1] = (float)tag;
            }
        }
    }
}

extern "C" void kernel_launch(void* const* d_in, const int* in_sizes, int n_in,
                              void* d_out, int out_size)
{
    const float* lp   = (const float*)d_in[0];
    const void*  mask = d_in[1];
    const void*  sc   = d_in[2];
    const void*  ec   = d_in[3];
    const void*  tc   = d_in[4];

    const int BT = in_sizes[1];      // B*T elements in mask
    int B = out_size - BT;           // out = [B] mlp + [B*T] tags
    if (B <= 0) B = 64;
    const int T = BT / B;

    size_t smem = (size_t)NS * CHUNK_B + (size_t)ARING * NTAG * 4
                + (size_t)T * NTAG + 64;
    cudaFuncSetAttribute(ConstrainedDecoder_kernel,
                         cudaFuncAttributeMaxDynamicSharedMemorySize, (int)smem);

    ConstrainedDecoder_kernel<<<B, 96, smem>>>(lp, mask, sc, ec, tc,
                                               (float*)d_out, B, T);
}